// round 1
// baseline (speedup 1.0000x reference)
#include <cuda_runtime.h>
#include <cuda_bf16.h>

// OTAM cumulative soft-min DP.
// dists: [200, 200, 32, 32] f32.  Output: [200, 200] f32 = cum[:, :, -1, -1].
// Per (q,s): 32x34 DP with lambda=0.5 soft-min recurrence.
//
// softmin_lambda(a,b)   = min(a,b) - L*ln2 * log2(1 + 2^(-(|a-b|)/(L*ln2)))
// softmin_lambda(a,b,p) = t - L*ln2 * log2(2^((t-a)c) + 2^((t-b)c) + 2^((t-p)c)), t=min3
// with c = 1/(L*ln2).  Stable: exp2 args <= 0, one term == 1.

#define QTOT 40000          // 200*200 problems
#define LROWS 32
#define MCOLS 32
#define MP 34               // padded columns (1..33 computed, col 0 stays 0)

__device__ __forceinline__ float ex2f(float x) {
    float y; asm("ex2.approx.f32 %0, %1;" : "=f"(y) : "f"(x)); return y;
}
__device__ __forceinline__ float lg2f(float x) {
    float y; asm("lg2.approx.f32 %0, %1;" : "=f"(y) : "f"(x)); return y;
}

// constant-index access into a float4 register array (folds at compile time)
#define ELT(arr, i) ((i)%4==0 ? arr[(i)/4].x : ((i)%4==1 ? arr[(i)/4].y : ((i)%4==2 ? arr[(i)/4].z : arr[(i)/4].w)))

__global__ void __launch_bounds__(128)
otam_kernel(const float* __restrict__ dists, float* __restrict__ out) {
    int p = blockIdx.x * blockDim.x + threadIdx.x;
    if (p >= QTOT) return;

    const float C2   = 2.8853900817779268f;   // 1/(lambda*ln2), lambda=0.5
    const float LLN2 = 0.34657359027997264f;  // lambda*ln2

    const float4* base = reinterpret_cast<const float4*>(dists) + (size_t)p * (LROWS * MCOLS / 4);

    float prev[MP];
    float4 cur[8], nxt[8];

    // ---- row 0: cumulative sum of padded row -> prev[0..33]
    #pragma unroll
    for (int i = 0; i < 8; i++) cur[i] = base[i];

    prev[0] = 0.0f;
    #pragma unroll
    for (int m = 1; m <= 32; m++) prev[m] = prev[m-1] + ELT(cur, m-1);
    prev[33] = prev[32];   // padded d = 0

    // prefetch row 1
    #pragma unroll
    for (int i = 0; i < 8; i++) cur[i] = base[8 + i];

    #pragma unroll 1
    for (int l = 1; l < LROWS; l++) {
        // prefetch next row while this row's serial chain runs
        if (l + 1 < LROWS) {
            const float4* rp = base + (l + 1) * 8;
            #pragma unroll
            for (int i = 0; i < 8; i++) nxt[i] = rp[i];
        }

        float cum   = 0.0f;      // carry; column 0 value is 0 and participates at m=1
        float aprev = prev[0];   // old prev[m-1]

        #pragma unroll
        for (int m = 1; m <= 33; m++) {
            const float dm = (m <= 32) ? ELT(cur, m-1) : 0.0f;
            const float pm = prev[m];          // old prev[m]
            float v;
            if (m == 1 || m == 33) {
                // 3-term soft-min: softmin(aprev, cum, pm)
                float t = fminf(fminf(aprev, cum), pm);
                float s = ex2f((t - aprev) * C2)
                        + ex2f((t - cum)   * C2)
                        + ex2f((t - pm)    * C2);
                v = dm + t - LLN2 * lg2f(s);
            } else {
                // 2-term soft-min: softmin(aprev, cum)
                float t = fminf(aprev, cum);
                float u = fmaxf(aprev, cum);
                float s = 1.0f + ex2f((t - u) * C2);
                v = dm + t - LLN2 * lg2f(s);
            }
            prev[m] = v;
            aprev = pm;   // becomes old prev[m] for next column
            cum = v;
        }

        // rotate prefetch buffer
        if (l + 1 < LROWS) {
            #pragma unroll
            for (int i = 0; i < 8; i++) cur[i] = nxt[i];
        }
    }

    out[p] = prev[33];
}

extern "C" void kernel_launch(void* const* d_in, const int* in_sizes, int n_in,
                              void* d_out, int out_size) {
    const float* dists = (const float*)d_in[0];
    float* out = (float*)d_out;
    int threads = 128;
    int blocks = (QTOT + threads - 1) / threads;
    otam_kernel<<<blocks, threads>>>(dists, out);
}

// round 2
// speedup vs baseline: 1.5292x; 1.5292x over previous
#include <cuda_runtime.h>
#include <cuda_bf16.h>

// OTAM cumulative soft-min DP.  dists: [200,200,32,32] f32 -> out [200,200] f32.
// Per problem: 32x34 padded DP, lambda = 0.5.
//   softmin(a,b)   = t - L*ln2*log2(1 + 2^((t-u)*C2)),  t=min,u=max
//   softmin(a,b,p) = t - L*ln2*log2(sum 2^((t-x)*C2)),  t=min3   (edge cols m=1,33)
//
// Round-2 structure: skewed row pipeline inside each thread. K rows are in
// flight simultaneously (row r is one column ahead of row r+1), giving K
// independent soft-min chains per thread to hide the ~56-cycle per-cell
// dependent latency. Rows 1..31 = 7 strips of K=4 + 1 strip of K=3.

#define QTOT 40000

__device__ __forceinline__ float ex2f(float x) {
    float y; asm("ex2.approx.f32 %0, %1;" : "=f"(y) : "f"(x)); return y;
}
__device__ __forceinline__ float lg2f(float x) {
    float y; asm("lg2.approx.f32 %0, %1;" : "=f"(y) : "f"(x)); return y;
}

// constant-index access into a float4 register array (folds at compile time)
#define ELT(arr, i) ((i)%4==0 ? (arr)[(i)/4].x : ((i)%4==1 ? (arr)[(i)/4].y : ((i)%4==2 ? (arr)[(i)/4].z : (arr)[(i)/4].w)))

// Process K consecutive DP rows with a column skew of 1 between adjacent rows.
// prev[0..33] holds the completed row above the strip on entry; on exit it
// holds the strip's bottom row. Column 0 of every row stays 0 (never written).
//
// State per in-flight row r at start of step t:
//   cum[r]  = v(r, t-1-r)   (last computed value)
//   cumP[r] = v(r, t-2-r)   (one column earlier)
// Row r computes v(r, m) with m = t-r, needing:
//   left        v(r,   m-1) = cum[r]
//   diag        v(r-1, m-1) = cumP[r-1]   (or prev[m-1] for r==0)
//   above(edge) v(r-1, m  ) = cum[r-1]    (or prev[m]   for r==0)
// Rows are processed bottom-up within a step so r-1's state is pre-update.
// Bottom row writes prev[m] at step m+K-1; row 0 last reads prev[m] at step
// m+1, so K>=3 guarantees no aliasing hazard.
template<int K>
__device__ __forceinline__ void run_strip(const float4* __restrict__ rp, float* prev) {
    const float C2   = 2.8853900817779268f;   // 1/(lambda*ln2)
    const float LLN2 = 0.34657359027997264f;  // lambda*ln2

    float4 d[K][8];
    #pragma unroll
    for (int r = 0; r < K; r++)
        #pragma unroll
        for (int i = 0; i < 8; i++) d[r][i] = rp[r * 8 + i];

    float cum[K], cumP[K];
    #pragma unroll
    for (int r = 0; r < K; r++) { cum[r] = 0.0f; cumP[r] = 0.0f; }

    #pragma unroll
    for (int t = 1; t <= 33 + K - 1; t++) {
        #pragma unroll
        for (int r = K - 1; r >= 0; r--) {
            const int m = t - r;
            if (m >= 1 && m <= 33) {
                const float dm = (m <= 32) ? ELT(d[r], m - 1) : 0.0f;
                const float a  = (r == 0) ? prev[m - 1] : cumP[r - 1];  // diag
                const float c  = cum[r];                                // left
                float v;
                if (m == 1 || m == 33) {
                    const float pm = (r == 0) ? prev[m] : cum[r - 1];   // above
                    float tm = fminf(fminf(a, c), pm);
                    float s  = ex2f((tm - a)  * C2)
                             + ex2f((tm - c)  * C2)
                             + ex2f((tm - pm) * C2);
                    v = fmaf(-LLN2, lg2f(s), dm + tm);
                } else {
                    float tm = fminf(a, c);
                    float u  = fmaxf(a, c);
                    float s  = 1.0f + ex2f((tm - u) * C2);
                    v = fmaf(-LLN2, lg2f(s), dm + tm);
                }
                cumP[r] = cum[r];
                cum[r]  = v;
                if (r == K - 1) prev[m] = v;
            }
        }
    }
}

__global__ void __launch_bounds__(64)
otam_kernel(const float* __restrict__ dists, float* __restrict__ out) {
    int p = blockIdx.x * 64 + threadIdx.x;
    if (p >= QTOT) return;

    const float4* base = reinterpret_cast<const float4*>(dists) + (size_t)p * 256;

    float prev[34];

    // row 0: cumulative sum of the padded row
    {
        float4 r0[8];
        #pragma unroll
        for (int i = 0; i < 8; i++) r0[i] = base[i];
        prev[0] = 0.0f;
        #pragma unroll
        for (int m = 1; m <= 32; m++) prev[m] = prev[m - 1] + ELT(r0, m - 1);
        prev[33] = prev[32];   // padded d = 0
    }

    // rows 1..28: seven strips of 4
    const float4* rp = base + 8;
    #pragma unroll 1
    for (int s = 0; s < 7; s++) {
        run_strip<4>(rp, prev);
        rp += 32;
    }
    // rows 29..31: one strip of 3
    run_strip<3>(rp, prev);

    out[p] = prev[33];
}

extern "C" void kernel_launch(void* const* d_in, const int* in_sizes, int n_in,
                              void* d_out, int out_size) {
    const float* dists = (const float*)d_in[0];
    float* out = (float*)d_out;
    int threads = 64;
    int blocks = (QTOT + threads - 1) / threads;
    otam_kernel<<<blocks, threads>>>(dists, out);
}

// round 4
// speedup vs baseline: 1.8899x; 1.2359x over previous
#include <cuda_runtime.h>
#include <cuda_bf16.h>
#include <cstdint>

// OTAM cumulative soft-min DP.  dists: [200,200,32,32] f32 -> out [200,200] f32.
// lambda = 0.5.
//   softmin(a,b)   = t - L*ln2*log2(1 + 2^((t-u)*C2)),  t=min,u=max
//   softmin(a,b,p) = t - L*ln2*log2(sum 2^((t-x)*C2)),  t=min3   (edge cols m=1,33)
//
// Round-4 structure (Round 3 + build fix):
//  * skewed row pipeline (K rows in flight per thread) for ILP
//  * per-strip shared-memory staging: block of 64 threads = 64 consecutive
//    problems; each stage's 64 x 512B chunks loaded with coalesced cp.async
//    (4 wavefronts/warp-load instead of 32), then threads read their own
//    chunk from smem (528B padded stride -> conflict-free LDS.128).
//  * single 33KB buffer -> 6 blocks/SM resident -> 12 warps/SM, one wave.

#define QTOT 40000
#define PPB 64                 // problems (= threads) per block
#define CHUNK_WORDS 132        // 128 data floats + 4 pad
#define BUF_WORDS (PPB * CHUNK_WORDS)   // 8448 floats = 33792 B

__device__ __forceinline__ float ex2f(float x) {
    float y; asm("ex2.approx.f32 %0, %1;" : "=f"(y) : "f"(x)); return y;
}
__device__ __forceinline__ float lg2f(float x) {
    float y; asm("lg2.approx.f32 %0, %1;" : "=f"(y) : "f"(x)); return y;
}
__device__ __forceinline__ void cp_async16(unsigned int dst, const void* src) {
    asm volatile("cp.async.cg.shared.global [%0], [%1], 16;\n"
                 :: "r"(dst), "l"(src) : "memory");
}

// constant-index access into a float4 (folds at compile time)
#define ELT4(v, k) ((k)==0 ? (v).x : ((k)==1 ? (v).y : ((k)==2 ? (v).z : (v).w)))

// K skewed rows in flight. rows[r*32 + j] = d(row r, col j) in smem.
// prev[0..33]: completed row above the strip on entry, bottom row on exit.
// Hazard rule: bottom row writes prev[m] at step m+K-1; row 0 last reads
// prev[m] at step m+1 -> K>=3 required.
template<int K>
__device__ __forceinline__ void run_strip(const float* __restrict__ rows, float* prev) {
    const float C2   = 2.8853900817779268f;   // 1/(lambda*ln2)
    const float LLN2 = 0.34657359027997264f;  // lambda*ln2

    float cum[K], cumP[K];
    #pragma unroll
    for (int r = 0; r < K; r++) { cum[r] = 0.0f; cumP[r] = 0.0f; }

    float4 d4[K];

    #pragma unroll
    for (int t = 1; t <= 33 + K - 1; t++) {
        #pragma unroll
        for (int r = K - 1; r >= 0; r--) {
            const int m = t - r;
            if (m >= 1 && m <= 33) {
                const int j = m - 1;
                if (j < 32 && (j & 3) == 0)
                    d4[r] = *reinterpret_cast<const float4*>(rows + r * 32 + j);
                const float dm = (j < 32) ? ELT4(d4[r], j & 3) : 0.0f;
                const float a  = (r == 0) ? prev[m - 1] : cumP[r - 1];  // diag
                const float c  = cum[r];                                // left
                float v;
                if (m == 1 || m == 33) {
                    const float pm = (r == 0) ? prev[m] : cum[r - 1];   // above
                    float tm = fminf(fminf(a, c), pm);
                    float s  = ex2f((tm - a)  * C2)
                             + ex2f((tm - c)  * C2)
                             + ex2f((tm - pm) * C2);
                    v = fmaf(-LLN2, lg2f(s), dm + tm);
                } else {
                    float tm = fminf(a, c);
                    float u  = fmaxf(a, c);
                    float s  = 1.0f + ex2f((tm - u) * C2);
                    v = fmaf(-LLN2, lg2f(s), dm + tm);
                }
                cumP[r] = cum[r];
                cum[r]  = v;
                if (r == K - 1) prev[m] = v;
            }
        }
    }
}

__global__ void __launch_bounds__(PPB)
otam_kernel(const float* __restrict__ dists, float* __restrict__ out) {
    extern __shared__ float smem[];          // BUF_WORDS floats
    const int t = threadIdx.x;
    const int pbase = blockIdx.x * PPB;      // 625 * 64 == 40000 exactly

    const unsigned int smem_u32 = (unsigned int)__cvta_generic_to_shared(smem);

    // Stage loader: rows [4s .. 4s+3] of all 64 problems, coalesced.
    // float4 index space: 64 chunks x 32 f4 = 2048; thread covers i*64+t.
    auto prefetch = [&](int stage) {
        #pragma unroll
        for (int i = 0; i < 32; i++) {
            const int idx  = i * PPB + t;
            const int q    = idx >> 5;       // chunk (local problem)
            const int lane = idx & 31;       // f4 within chunk
            const float* g = dists + (size_t)(pbase + q) * 1024 + stage * 128 + lane * 4;
            const unsigned int s = smem_u32 + (unsigned int)(q * CHUNK_WORDS + lane * 4) * 4u;
            cp_async16(s, g);
        }
        asm volatile("cp.async.commit_group;\n" ::);
    };

    float prev[34];
    const float* ch = smem + t * CHUNK_WORDS;   // this thread's chunk

    // ---- stage 0: rows 0..3
    prefetch(0);
    asm volatile("cp.async.wait_group 0;\n" ::);
    __syncthreads();
    {
        // row 0: cumulative sum of padded row
        float4 r0[8];
        #pragma unroll
        for (int i = 0; i < 8; i++)
            r0[i] = *reinterpret_cast<const float4*>(ch + 4 * i);
        prev[0] = 0.0f;
        #pragma unroll
        for (int m = 1; m <= 32; m++) {
            const int j = m - 1;
            prev[m] = prev[m - 1] + ELT4(r0[j >> 2], j & 3);
        }
        prev[33] = prev[32];    // padded d = 0
    }
    run_strip<3>(ch + 32, prev);        // rows 1..3

    // ---- stages 1..7: rows 4s..4s+3, K=4
    #pragma unroll 1
    for (int s = 1; s < 8; s++) {
        __syncthreads();                // all threads done with previous stage's data
        prefetch(s);
        asm volatile("cp.async.wait_group 0;\n" ::);
        __syncthreads();
        run_strip<4>(ch, prev);
    }

    out[pbase + t] = prev[33];
}

extern "C" void kernel_launch(void* const* d_in, const int* in_sizes, int n_in,
                              void* d_out, int out_size) {
    const float* dists = (const float*)d_in[0];
    float* out = (float*)d_out;
    const int blocks = QTOT / PPB;      // 625
    const size_t shmem = BUF_WORDS * sizeof(float);   // 33792 B
    otam_kernel<<<blocks, PPB, shmem>>>(dists, out);
}

// round 5
// speedup vs baseline: 2.1478x; 1.1365x over previous
#include <cuda_runtime.h>
#include <cuda_bf16.h>
#include <cstdint>

// OTAM cumulative soft-min DP.  dists: [200,200,32,32] f32 -> out [200,200] f32.
// lambda = 0.5.
//   softmin(a,b)   = t - L*ln2*log2(1 + 2^((t-u)*C2)),  t=min,u=max
//   softmin(a,b,p) = t - L*ln2*log2(sum 2^((t-x)*C2)),  t=min3   (edge cols m=1,33)
//
// Round-5: fix SMSP starvation. wid%4 -> SMSP, so 64-thread blocks used only
// schedulers 0,1. Now blockDim=128 (all 4 SMSPs) with PER-WARP staging:
// each warp owns 32 problems + its own 16.9KB smem region + its own cp.async
// groups; __syncwarp only, no __syncthreads -> warps fully decoupled.

#define QTOT 40000
#define PPW 32                  // problems per warp
#define PPB 128                 // threads (= problems) per block, 4 warps
#define CHUNK_WORDS 132         // 128 data floats + 4 pad (528B, conflict-free LDS.128)
#define WARP_WORDS (PPW * CHUNK_WORDS)   // 4224 floats = 16896 B per warp
#define BUF_WORDS (4 * WARP_WORDS)       // 67584 B per block

__device__ __forceinline__ float ex2f(float x) {
    float y; asm("ex2.approx.f32 %0, %1;" : "=f"(y) : "f"(x)); return y;
}
__device__ __forceinline__ float lg2f(float x) {
    float y; asm("lg2.approx.f32 %0, %1;" : "=f"(y) : "f"(x)); return y;
}
__device__ __forceinline__ void cp_async16(unsigned int dst, const void* src) {
    asm volatile("cp.async.cg.shared.global [%0], [%1], 16;\n"
                 :: "r"(dst), "l"(src) : "memory");
}

// constant-index access into a float4 (folds at compile time)
#define ELT4(v, k) ((k)==0 ? (v).x : ((k)==1 ? (v).y : ((k)==2 ? (v).z : (v).w)))

// K skewed rows in flight (row r one column ahead of row r+1): K independent
// soft-min chains per thread hide the ~55-cycle per-cell dependent latency.
// rows[r*32 + j] = d(row r, col j) in this thread's smem chunk.
// prev[0..33]: completed row above the strip on entry, bottom row on exit.
// Hazard rule: bottom row writes prev[m] at step m+K-1; row 0 last reads
// prev[m] at step m+1 -> K>=3 required.
template<int K>
__device__ __forceinline__ void run_strip(const float* __restrict__ rows, float* prev) {
    const float C2   = 2.8853900817779268f;   // 1/(lambda*ln2)
    const float LLN2 = 0.34657359027997264f;  // lambda*ln2

    float cum[K], cumP[K];
    #pragma unroll
    for (int r = 0; r < K; r++) { cum[r] = 0.0f; cumP[r] = 0.0f; }

    float4 d4[K];

    #pragma unroll
    for (int t = 1; t <= 33 + K - 1; t++) {
        #pragma unroll
        for (int r = K - 1; r >= 0; r--) {
            const int m = t - r;
            if (m >= 1 && m <= 33) {
                const int j = m - 1;
                if (j < 32 && (j & 3) == 0)
                    d4[r] = *reinterpret_cast<const float4*>(rows + r * 32 + j);
                const float dm = (j < 32) ? ELT4(d4[r], j & 3) : 0.0f;
                const float a  = (r == 0) ? prev[m - 1] : cumP[r - 1];  // diag
                const float c  = cum[r];                                // left
                float v;
                if (m == 1 || m == 33) {
                    const float pm = (r == 0) ? prev[m] : cum[r - 1];   // above
                    float tm = fminf(fminf(a, c), pm);
                    float s  = ex2f((tm - a)  * C2)
                             + ex2f((tm - c)  * C2)
                             + ex2f((tm - pm) * C2);
                    v = fmaf(-LLN2, lg2f(s), dm + tm);
                } else {
                    float tm = fminf(a, c);
                    float u  = fmaxf(a, c);
                    float s  = 1.0f + ex2f((tm - u) * C2);
                    v = fmaf(-LLN2, lg2f(s), dm + tm);
                }
                cumP[r] = cum[r];
                cum[r]  = v;
                if (r == K - 1) prev[m] = v;
            }
        }
    }
}

__global__ void __launch_bounds__(PPB)
otam_kernel(const float* __restrict__ dists, float* __restrict__ out) {
    extern __shared__ float smem[];          // BUF_WORDS floats
    const int lane = threadIdx.x & 31;
    const int wid  = threadIdx.x >> 5;

    // This warp's 32 consecutive problems. QTOT % 32 == 0, so warps are
    // entirely in or out (block 312: warps 2,3 exit; no partial warps).
    const int pw = blockIdx.x * PPB + wid * PPW;
    if (pw >= QTOT) return;

    float* wsm = smem + wid * WARP_WORDS;                 // this warp's region
    const unsigned int wsm_u32 =
        (unsigned int)__cvta_generic_to_shared(wsm);

    // Per-warp stage loader: rows [4s..4s+3] of 32 problems, coalesced.
    // cp.async i: problem i's 32 float4s spread across lanes (contiguous 512B).
    auto prefetch = [&](int stage) {
        #pragma unroll
        for (int i = 0; i < PPW; i++) {
            const float* g = dists + (size_t)(pw + i) * 1024 + stage * 128 + lane * 4;
            const unsigned int s = wsm_u32 + (unsigned int)(i * CHUNK_WORDS + lane * 4) * 4u;
            cp_async16(s, g);
        }
        asm volatile("cp.async.commit_group;\n" ::);
    };

    float prev[34];
    const float* ch = wsm + lane * CHUNK_WORDS;           // this thread's chunk

    // ---- stage 0: rows 0..3
    prefetch(0);
    asm volatile("cp.async.wait_group 0;\n" ::);
    __syncwarp();
    {
        // row 0: cumulative sum of padded row
        float4 r0[8];
        #pragma unroll
        for (int i = 0; i < 8; i++)
            r0[i] = *reinterpret_cast<const float4*>(ch + 4 * i);
        prev[0] = 0.0f;
        #pragma unroll
        for (int m = 1; m <= 32; m++) {
            const int j = m - 1;
            prev[m] = prev[m - 1] + ELT4(r0[j >> 2], j & 3);
        }
        prev[33] = prev[32];    // padded d = 0
    }
    run_strip<3>(ch + 32, prev);        // rows 1..3

    // ---- stages 1..7: rows 4s..4s+3, K=4
    #pragma unroll 1
    for (int s = 1; s < 8; s++) {
        __syncwarp();                   // all lanes done with previous stage's data
        prefetch(s);
        asm volatile("cp.async.wait_group 0;\n" ::);
        __syncwarp();
        run_strip<4>(ch, prev);
    }

    out[pw + lane] = prev[33];
}

extern "C" void kernel_launch(void* const* d_in, const int* in_sizes, int n_in,
                              void* d_out, int out_size) {
    const float* dists = (const float*)d_in[0];
    float* out = (float*)d_out;
    const int blocks = (QTOT + PPB - 1) / PPB;            // 313
    const size_t shmem = BUF_WORDS * sizeof(float);       // 67584 B
    cudaFuncSetAttribute(otam_kernel, cudaFuncAttributeMaxDynamicSharedMemorySize,
                         (int)shmem);
    otam_kernel<<<blocks, PPB, shmem>>>(dists, out);
}